// round 3
// baseline (speedup 1.0000x reference)
#include <cuda_runtime.h>

// ContrastiveLearningLoss: out = sum_i c_i * d_i + exp(d_i),
//   d_i = dot(z_a[i], z_b[i]),  c_i = n-3 for i<n-1, n-2 for i=n-1.
// Pure HBM-bound streaming reduction (128 MiB read).

#define D_DIM      256
#define NBLOCKS    2048
#define NTHREADS   256
#define WARPS_PER_BLOCK (NTHREADS / 32)

__device__ double g_partials[NBLOCKS];

__global__ __launch_bounds__(NTHREADS)
void cl_loss_dot_kernel(const float* __restrict__ za,
                        const float* __restrict__ zb,
                        int n)
{
    const int warp = threadIdx.x >> 5;
    const int lane = threadIdx.x & 31;

    double acc = 0.0;

    for (int row = blockIdx.x * WARPS_PER_BLOCK + warp; row < n;
         row += gridDim.x * WARPS_PER_BLOCK) {
        const float4* __restrict__ a =
            reinterpret_cast<const float4*>(za + (size_t)row * D_DIM);
        const float4* __restrict__ b =
            reinterpret_cast<const float4*>(zb + (size_t)row * D_DIM);

        // D=256 -> 64 float4 per row; lane handles indices {lane, lane+32}.
        // 8 independent LDG.128 issued up front -> good MLP.
        float4 a0 = a[lane];
        float4 b0 = b[lane];
        float4 a1 = a[lane + 32];
        float4 b1 = b[lane + 32];

        float s = a0.x * b0.x + a0.y * b0.y + a0.z * b0.z + a0.w * b0.w
                + a1.x * b1.x + a1.y * b1.y + a1.z * b1.z + a1.w * b1.w;

        // warp tree reduce
        #pragma unroll
        for (int off = 16; off > 0; off >>= 1)
            s += __shfl_xor_sync(0xffffffffu, s, off);

        if (lane == 0) {
            double coeff = (row == n - 1) ? (double)(n - 2) : (double)(n - 3);
            acc += coeff * (double)s + (double)expf(s);
        }
    }

    __shared__ double sm[WARPS_PER_BLOCK];
    if (lane == 0) sm[warp] = acc;
    __syncthreads();

    if (threadIdx.x == 0) {
        double t = 0.0;
        #pragma unroll
        for (int i = 0; i < WARPS_PER_BLOCK; ++i) t += sm[i];
        g_partials[blockIdx.x] = t;
    }
}

__global__ __launch_bounds__(256)
void cl_loss_reduce_kernel(float* __restrict__ out)
{
    __shared__ double sm[256];
    double t = 0.0;
    for (int i = threadIdx.x; i < NBLOCKS; i += 256)
        t += g_partials[i];
    sm[threadIdx.x] = t;
    __syncthreads();
    #pragma unroll
    for (int s = 128; s > 0; s >>= 1) {
        if (threadIdx.x < s) sm[threadIdx.x] += sm[threadIdx.x + s];
        __syncthreads();
    }
    if (threadIdx.x == 0) out[0] = (float)sm[0];
}

extern "C" void kernel_launch(void* const* d_in, const int* in_sizes, int n_in,
                              void* d_out, int out_size)
{
    const float* za = (const float*)d_in[0];
    const float* zb = (const float*)d_in[1];
    float* out = (float*)d_out;

    const int n = in_sizes[0] / D_DIM;  // 65536

    cl_loss_dot_kernel<<<NBLOCKS, NTHREADS>>>(za, zb, n);
    cl_loss_reduce_kernel<<<1, 256>>>(out);
}